// round 1
// baseline (speedup 1.0000x reference)
#include <cuda_runtime.h>
#include <cuda_bf16.h>
#include <cstdint>

// Problem constants
#define B_  64
#define N_  10000
#define D_  66
#define F_  4224          // D_*B_
#define E_  160000
#define O_  64
#define DM_ 330           // D_*5
#define FT_ 1056          // feature tile (floats) -> 4 tiles
#define F4_ 1056          // floats4 per row = F_/4

// ---------------- scratch (static device allocations, allowed) ----------------
__device__ float g_x0 [42240000];
__device__ float g_x1a[42240000];
__device__ float g_ya [42240000];
__device__ float g_x1b[42240000];
__device__ float g_yb [42240000];
__device__ float g_wmod[DM_ * O_];

__device__ int   g_cnt [2][N_];
__device__ int   g_rp  [2][N_ + 1];
__device__ int   g_cur [2][N_];
__device__ int   g_colS[2][E_];
__device__ float g_valS[2][E_];

// ---------------- f32x2 helpers ----------------
__device__ __forceinline__ unsigned long long fma2(unsigned long long a,
                                                   unsigned long long b,
                                                   unsigned long long c) {
    unsigned long long d;
    asm("fma.rn.f32x2 %0, %1, %2, %3;" : "=l"(d) : "l"(a), "l"(b), "l"(c));
    return d;
}
__device__ __forceinline__ unsigned long long pack2(float x, float y) {
    unsigned long long d;
    asm("mov.b64 %0, {%1, %2};" : "=l"(d) : "f"(x), "f"(y));
    return d;
}
__device__ __forceinline__ float2 unpack2(unsigned long long a) {
    float2 r;
    asm("mov.b64 {%0, %1}, %2;" : "=f"(r.x), "=f"(r.y) : "l"(a));
    return r;
}

// ---------------- kernels ----------------

// W' transform: fold x2 = 2*spmm(x1) - x0 into the weights.
// row r = d*5+m of W'[330][64]:
//   m=0: W0 - W2 - W4 ; m=2: 2*W2 ; m=4: 2*W4 ; m=1,3: copy
__global__ void k_wmod(const float* __restrict__ w, float* __restrict__ wm) {
    int i = blockIdx.x * blockDim.x + threadIdx.x;
    if (i >= DM_ * O_) return;
    int r = i >> 6, o = i & 63;
    int d = r / 5, m = r % 5;
    float v;
    if (m == 0)
        v = w[(d * 5 + 0) * 64 + o] - w[(d * 5 + 2) * 64 + o] - w[(d * 5 + 4) * 64 + o];
    else if (m == 2 || m == 4)
        v = 2.0f * w[i];
    else
        v = w[i];
    wm[i] = v;
}

// x0[n, d*64 + b] = inputs[b, n*66 + d]
__global__ void k_transpose(const float* __restrict__ in, float* __restrict__ x0) {
    __shared__ float s[B_ * 67];
    int n = blockIdx.x;
    for (int idx = threadIdx.x; idx < B_ * D_; idx += blockDim.x) {
        int b = idx / D_, d = idx - b * D_;
        s[b * 67 + d] = in[(size_t)b * (N_ * D_) + (size_t)n * D_ + d];
    }
    __syncthreads();
    float* dst = x0 + (size_t)n * F_;
    for (int f = threadIdx.x; f < F_; f += blockDim.x) {
        int d = f >> 6, b = f & 63;
        dst[f] = s[b * 67 + d];
    }
}

__global__ void k_zero_int(int* __restrict__ p, int n) {
    int i = blockIdx.x * blockDim.x + threadIdx.x;
    if (i < n) p[i] = 0;
}

__global__ void k_hist(const int* __restrict__ rows, int* __restrict__ cnt) {
    int e = blockIdx.x * blockDim.x + threadIdx.x;
    if (e < E_) atomicAdd(&cnt[rows[e]], 1);
}

// 1-block exclusive scan of cnt[N] -> rowptr[N+1], cursor[N]
__global__ void k_scan(const int* __restrict__ cnt, int* __restrict__ rowptr,
                       int* __restrict__ cursor) {
    __shared__ int part[1024];
    const int CH = 10;
    int t = threadIdx.x;
    int base = t * CH;
    int loc[CH];
    int s = 0;
#pragma unroll
    for (int j = 0; j < CH; j++) {
        int i = base + j;
        int c = (i < N_) ? cnt[i] : 0;
        loc[j] = c;
        s += c;
    }
    part[t] = s;
    __syncthreads();
    for (int off = 1; off < 1024; off <<= 1) {
        int v = (t >= off) ? part[t - off] : 0;
        __syncthreads();
        part[t] += v;
        __syncthreads();
    }
    int off0 = (t > 0) ? part[t - 1] : 0;
#pragma unroll
    for (int j = 0; j < CH; j++) {
        int i = base + j;
        if (i < N_) {
            rowptr[i] = off0;
            cursor[i] = off0;
            off0 += loc[j];
        }
    }
    if (t == 1023) rowptr[N_] = part[1023];
}

__global__ void k_scatter(const int* __restrict__ rows, const int* __restrict__ cols,
                          const float* __restrict__ vals, int* __restrict__ cursor,
                          int* __restrict__ colS, float* __restrict__ valS) {
    int e = blockIdx.x * blockDim.x + threadIdx.x;
    if (e < E_) {
        int r = rows[e];
        int p = atomicAdd(&cursor[r], 1);
        colS[p] = cols[e];
        valS[p] = vals[e];
    }
}

// CSR SpMM: one block = (row r, feature tile). 256 threads cover 264 float4.
__global__ void __launch_bounds__(256) k_spmm(
    const int* __restrict__ rowptr, const int* __restrict__ colS,
    const float* __restrict__ valS, const float* __restrict__ x,
    float* __restrict__ y) {
    __shared__ int   sc[256];
    __shared__ float sv[256];
    int r = blockIdx.x;
    int fb4 = blockIdx.y * (FT_ / 4);  // float4 base within row
    int t = threadIdx.x;
    int e0 = rowptr[r], e1 = rowptr[r + 1];

    float4 a0 = make_float4(0.f, 0.f, 0.f, 0.f);
    float4 a1 = make_float4(0.f, 0.f, 0.f, 0.f);
    const float4* xb = reinterpret_cast<const float4*>(x) + fb4;

    for (int es = e0; es < e1; es += 256) {
        int ne = min(256, e1 - es);
        if (t < ne) { sc[t] = colS[es + t]; sv[t] = valS[es + t]; }
        __syncthreads();
        int j = 0;
        for (; j + 1 < ne; j += 2) {
            int c0 = sc[j], c1 = sc[j + 1];
            float v0 = sv[j], v1 = sv[j + 1];
            const float4* xr0 = xb + (size_t)c0 * F4_;
            const float4* xr1 = xb + (size_t)c1 * F4_;
            float4 p = xr0[t];
            float4 q = xr1[t];
            float4 p2, q2;
            if (t < 8) { p2 = xr0[256 + t]; q2 = xr1[256 + t]; }
            a0.x += v0 * p.x; a0.y += v0 * p.y; a0.z += v0 * p.z; a0.w += v0 * p.w;
            a0.x += v1 * q.x; a0.y += v1 * q.y; a0.z += v1 * q.z; a0.w += v1 * q.w;
            if (t < 8) {
                a1.x += v0 * p2.x; a1.y += v0 * p2.y; a1.z += v0 * p2.z; a1.w += v0 * p2.w;
                a1.x += v1 * q2.x; a1.y += v1 * q2.y; a1.z += v1 * q2.z; a1.w += v1 * q2.w;
            }
        }
        if (j < ne) {
            int c0 = sc[j];
            float v0 = sv[j];
            const float4* xr0 = xb + (size_t)c0 * F4_;
            float4 p = xr0[t];
            a0.x += v0 * p.x; a0.y += v0 * p.y; a0.z += v0 * p.z; a0.w += v0 * p.w;
            if (t < 8) {
                float4 p2 = xr0[256 + t];
                a1.x += v0 * p2.x; a1.y += v0 * p2.y; a1.z += v0 * p2.z; a1.w += v0 * p2.w;
            }
        }
        __syncthreads();
    }
    float4* yr = reinterpret_cast<float4*>(y) + (size_t)r * F4_ + fb4;
    yr[t] = a0;
    if (t < 8) yr[256 + t] = a1;
}

// GEMM: per node n, out[b, n*64+o] = sum_{d,m} x_m[n, d*64+b] * W'[d*5+m, o] + bias[o]
// 128 threads, each computes a 4b x 8o tile with packed f32x2 (packed over o).
__global__ void __launch_bounds__(128) k_gemm(
    const float* __restrict__ x0, const float* __restrict__ x1a,
    const float* __restrict__ ya, const float* __restrict__ x1b,
    const float* __restrict__ yb, const float* __restrict__ wm,
    const float* __restrict__ bias, float* __restrict__ out) {
    extern __shared__ float sm[];
    float* sx = sm;            // [5][66][64] = 21120
    float* sw = sm + 21120;    // [330][64]  = 21120

    int n = blockIdx.x;
    int t = threadIdx.x;

    const float* xs[5] = {x0, x1a, ya, x1b, yb};
#pragma unroll
    for (int m = 0; m < 5; m++) {
        const float* src = xs[m] + (size_t)n * F_;
        for (int i = t; i < F_; i += 128) sx[m * F_ + i] = src[i];
    }
    for (int i = t; i < DM_ * O_; i += 128) sw[i] = wm[i];
    __syncthreads();

    int b0 = (t >> 3) * 4;   // 16 groups of 4 b
    int o0 = (t & 7) * 8;    // 8 groups of 8 o

    unsigned long long acc[4][4];
#pragma unroll
    for (int bi = 0; bi < 4; bi++)
#pragma unroll
        for (int op = 0; op < 4; op++) acc[bi][op] = 0ULL;

    for (int d = 0; d < D_; d++) {
#pragma unroll
        for (int m = 0; m < 5; m++) {
            float4 xv = *reinterpret_cast<const float4*>(&sx[m * F_ + (d << 6) + b0]);
            unsigned long long xx[4];
            xx[0] = pack2(xv.x, xv.x);
            xx[1] = pack2(xv.y, xv.y);
            xx[2] = pack2(xv.z, xv.z);
            xx[3] = pack2(xv.w, xv.w);
            const unsigned long long* wp =
                reinterpret_cast<const unsigned long long*>(&sw[(d * 5 + m) * 64 + o0]);
            unsigned long long w0 = wp[0], w1 = wp[1], w2 = wp[2], w3 = wp[3];
#pragma unroll
            for (int bi = 0; bi < 4; bi++) {
                acc[bi][0] = fma2(xx[bi], w0, acc[bi][0]);
                acc[bi][1] = fma2(xx[bi], w1, acc[bi][1]);
                acc[bi][2] = fma2(xx[bi], w2, acc[bi][2]);
                acc[bi][3] = fma2(xx[bi], w3, acc[bi][3]);
            }
        }
    }

    float bs[8];
#pragma unroll
    for (int k = 0; k < 8; k++) bs[k] = bias[o0 + k];

#pragma unroll
    for (int bi = 0; bi < 4; bi++) {
        float* orow = out + (size_t)(b0 + bi) * ((size_t)N_ * O_) + (size_t)n * O_ + o0;
#pragma unroll
        for (int op = 0; op < 4; op++) {
            float2 v = unpack2(acc[bi][op]);
            float2 w;
            w.x = v.x + bs[op * 2];
            w.y = v.y + bs[op * 2 + 1];
            *reinterpret_cast<float2*>(&orow[op * 2]) = w;
        }
    }
}

// ---------------- launch ----------------
extern "C" void kernel_launch(void* const* d_in, const int* in_sizes, int n_in,
                              void* d_out, int out_size) {
    const float* inputs = (const float*)d_in[0];
    const float* weight = (const float*)d_in[2];
    const float* biases = (const float*)d_in[3];
    const float* vals0  = (const float*)d_in[4];
    const float* vals1  = (const float*)d_in[5];
    const int*   rows0  = (const int*)d_in[6];
    const int*   cols0  = (const int*)d_in[7];
    const int*   rows1  = (const int*)d_in[8];
    const int*   cols1  = (const int*)d_in[9];
    float* out = (float*)d_out;

    float *x0, *x1a, *ya, *x1b, *yb, *wm, *valS;
    int *cnt, *rp, *cur, *colS;
    cudaGetSymbolAddress((void**)&x0,  g_x0);
    cudaGetSymbolAddress((void**)&x1a, g_x1a);
    cudaGetSymbolAddress((void**)&ya,  g_ya);
    cudaGetSymbolAddress((void**)&x1b, g_x1b);
    cudaGetSymbolAddress((void**)&yb,  g_yb);
    cudaGetSymbolAddress((void**)&wm,  g_wmod);
    cudaGetSymbolAddress((void**)&cnt,  g_cnt);
    cudaGetSymbolAddress((void**)&rp,   g_rp);
    cudaGetSymbolAddress((void**)&cur,  g_cur);
    cudaGetSymbolAddress((void**)&colS, g_colS);
    cudaGetSymbolAddress((void**)&valS, g_valS);

    const int* rowsArr[2] = {rows0, rows1};
    const int* colsArr[2] = {cols0, cols1};
    const float* valsArr[2] = {vals0, vals1};

    k_wmod<<<(DM_ * O_ + 255) / 256, 256>>>(weight, wm);
    k_transpose<<<N_, 256>>>(inputs, x0);

    for (int s = 0; s < 2; s++) {
        int* cnt_s  = cnt + (size_t)s * N_;
        int* rp_s   = rp + (size_t)s * (N_ + 1);
        int* cur_s  = cur + (size_t)s * N_;
        int* colS_s = colS + (size_t)s * E_;
        float* valS_s = valS + (size_t)s * E_;
        k_zero_int<<<(N_ + 255) / 256, 256>>>(cnt_s, N_);
        k_hist<<<(E_ + 255) / 256, 256>>>(rowsArr[s], cnt_s);
        k_scan<<<1, 1024>>>(cnt_s, rp_s, cur_s);
        k_scatter<<<(E_ + 255) / 256, 256>>>(rowsArr[s], colsArr[s], valsArr[s],
                                             cur_s, colS_s, valS_s);
    }

    dim3 gs(N_, 4);
    int* rp0 = rp;
    int* rp1 = rp + (N_ + 1);
    int* colS0 = colS;
    int* colS1 = colS + E_;
    float* valS0 = valS;
    float* valS1 = valS + E_;
    k_spmm<<<gs, 256>>>(rp0, colS0, valS0, x0, x1a);
    k_spmm<<<gs, 256>>>(rp0, colS0, valS0, x1a, ya);
    k_spmm<<<gs, 256>>>(rp1, colS1, valS1, x0, x1b);
    k_spmm<<<gs, 256>>>(rp1, colS1, valS1, x1b, yb);

    const int smem_gemm = (21120 + 21120) * 4;  // 168960 B
    cudaFuncSetAttribute(k_gemm, cudaFuncAttributeMaxDynamicSharedMemorySize, smem_gemm);
    k_gemm<<<N_, 128, smem_gemm>>>(x0, x1a, ya, x1b, yb, wm, biases, out);
}

// round 3
// speedup vs baseline: 1.7034x; 1.7034x over previous
#include <cuda_runtime.h>
#include <cuda_fp16.h>
#include <cstdint>

// Problem constants
#define B_  64
#define N_  10000
#define D_  66
#define F_  4224          // D_*B_
#define E_  160000
#define O_  64
#define DM_ 330           // D_*5
#define ROWU4 528         // uint4 (8 halves) per row = F_/8
#define U4T 264           // uint4 per feature tile (2 tiles)

// ---------------- scratch (static device allocations, allowed) ----------------
__device__ float  g_x0 [42240000];
__device__ float  g_x1a[42240000];
__device__ float  g_ya [42240000];
__device__ float  g_x1b[42240000];
__device__ float  g_yb [42240000];
__device__ __half g_x0h [42240000];
__device__ __half g_xht [42240000];   // reused: x1a fp16, then x1b fp16
__device__ float  g_wmod[DM_ * O_];

__device__ int   g_cnt [2][N_];
__device__ int   g_rp  [2][N_ + 1];
__device__ int   g_cur [2][N_];
__device__ int   g_colS[2][E_];
__device__ float g_valS[2][E_];

// ---------------- f32x2 helpers ----------------
__device__ __forceinline__ unsigned long long fma2(unsigned long long a,
                                                   unsigned long long b,
                                                   unsigned long long c) {
    unsigned long long d;
    asm("fma.rn.f32x2 %0, %1, %2, %3;" : "=l"(d) : "l"(a), "l"(b), "l"(c));
    return d;
}
__device__ __forceinline__ unsigned long long pack2(float x, float y) {
    unsigned long long d;
    asm("mov.b64 %0, {%1, %2};" : "=l"(d) : "f"(x), "f"(y));
    return d;
}
__device__ __forceinline__ float2 unpack2(unsigned long long a) {
    float2 r;
    asm("mov.b64 {%0, %1}, %2;" : "=f"(r.x), "=f"(r.y) : "l"(a));
    return r;
}

// ---------------- kernels ----------------

// W' transform: fold x2 = 2*spmm(x1) - x0 into the weights.
__global__ void k_wmod(const float* __restrict__ w, float* __restrict__ wm) {
    int i = blockIdx.x * blockDim.x + threadIdx.x;
    if (i >= DM_ * O_) return;
    int r = i >> 6, o = i & 63;
    int d = r / 5, m = r % 5;
    float v;
    if (m == 0)
        v = w[(d * 5 + 0) * 64 + o] - w[(d * 5 + 2) * 64 + o] - w[(d * 5 + 4) * 64 + o];
    else if (m == 2 || m == 4)
        v = 2.0f * w[i];
    else
        v = w[i];
    wm[i] = v;
}

// x0[n, d*64 + b] = inputs[b, n*66 + d]; also fp16 copy
__global__ void k_transpose(const float* __restrict__ in, float* __restrict__ x0,
                            __half* __restrict__ x0h) {
    __shared__ float s[B_ * 67];
    int n = blockIdx.x;
    for (int idx = threadIdx.x; idx < B_ * D_; idx += blockDim.x) {
        int b = idx / D_, d = idx - b * D_;
        s[b * 67 + d] = in[(size_t)b * (N_ * D_) + (size_t)n * D_ + d];
    }
    __syncthreads();
    float* dst = x0 + (size_t)n * F_;
    __half* dsth = x0h + (size_t)n * F_;
    for (int f = threadIdx.x; f < F_; f += blockDim.x) {
        int d = f >> 6, b = f & 63;
        float v = s[b * 67 + d];
        dst[f] = v;
        dsth[f] = __float2half_rn(v);
    }
}

__global__ void k_zero_int(int* __restrict__ p, int n) {
    int i = blockIdx.x * blockDim.x + threadIdx.x;
    if (i < n) p[i] = 0;
}

__global__ void k_hist(const int* __restrict__ rows, int* __restrict__ cnt) {
    int e = blockIdx.x * blockDim.x + threadIdx.x;
    if (e < E_) atomicAdd(&cnt[rows[e]], 1);
}

// 1-block exclusive scan of cnt[N] -> rowptr[N+1], cursor[N]
__global__ void k_scan(const int* __restrict__ cnt, int* __restrict__ rowptr,
                       int* __restrict__ cursor) {
    __shared__ int part[1024];
    const int CH = 10;
    int t = threadIdx.x;
    int base = t * CH;
    int loc[CH];
    int s = 0;
#pragma unroll
    for (int j = 0; j < CH; j++) {
        int i = base + j;
        int c = (i < N_) ? cnt[i] : 0;
        loc[j] = c;
        s += c;
    }
    part[t] = s;
    __syncthreads();
    for (int off = 1; off < 1024; off <<= 1) {
        int v = (t >= off) ? part[t - off] : 0;
        __syncthreads();
        part[t] += v;
        __syncthreads();
    }
    int off0 = (t > 0) ? part[t - 1] : 0;
#pragma unroll
    for (int j = 0; j < CH; j++) {
        int i = base + j;
        if (i < N_) {
            rowptr[i] = off0;
            cursor[i] = off0;
            off0 += loc[j];
        }
    }
    if (t == 1023) rowptr[N_] = part[1023];
}

__global__ void k_scatter(const int* __restrict__ rows, const int* __restrict__ cols,
                          const float* __restrict__ vals, int* __restrict__ cursor,
                          int* __restrict__ colS, float* __restrict__ valS) {
    int e = blockIdx.x * blockDim.x + threadIdx.x;
    if (e < E_) {
        int r = rows[e];
        int p = atomicAdd(&cursor[r], 1);
        colS[p] = cols[e];
        valS[p] = vals[e];
    }
}

// CSR SpMM with fp16 gather operand, fp32 accumulate.
// block = (row r, tile of 264 uint4 = 2112 feats). 288 threads, 264 active.
// Writes fp32 y always; fp16 yh when non-null (needed as next gather source).
__global__ void __launch_bounds__(288) k_spmm_h(
    const int* __restrict__ rowptr, const int* __restrict__ colS,
    const float* __restrict__ valS, const __half* __restrict__ xh,
    float* __restrict__ y, __half* __restrict__ yh) {
    __shared__ int   sc[288];
    __shared__ float sv[288];
    int r = blockIdx.x;
    int t = threadIdx.x;
    int i4 = blockIdx.y * U4T + t;          // uint4 index within row
    bool act = (t < U4T);
    int e0 = rowptr[r], e1 = rowptr[r + 1];

    float a0 = 0.f, a1 = 0.f, a2 = 0.f, a3 = 0.f;
    float a4 = 0.f, a5 = 0.f, a6 = 0.f, a7 = 0.f;
    const uint4* xb = reinterpret_cast<const uint4*>(xh);

    for (int es = e0; es < e1; es += 288) {
        int ne = min(288, e1 - es);
        if (t < ne) { sc[t] = colS[es + t]; sv[t] = valS[es + t]; }
        __syncthreads();
        if (act) {
#pragma unroll 4
            for (int j = 0; j < ne; j++) {
                int c = sc[j];
                float v = sv[j];
                uint4 p = __ldg(xb + (size_t)c * ROWU4 + i4);
                float2 f0 = __half22float2(*reinterpret_cast<half2*>(&p.x));
                float2 f1 = __half22float2(*reinterpret_cast<half2*>(&p.y));
                float2 f2 = __half22float2(*reinterpret_cast<half2*>(&p.z));
                float2 f3 = __half22float2(*reinterpret_cast<half2*>(&p.w));
                a0 += v * f0.x; a1 += v * f0.y;
                a2 += v * f1.x; a3 += v * f1.y;
                a4 += v * f2.x; a5 += v * f2.y;
                a6 += v * f3.x; a7 += v * f3.y;
            }
        }
        __syncthreads();
    }
    if (act) {
        float4* yp = reinterpret_cast<float4*>(y) + (size_t)r * (F_ / 4) + (size_t)i4 * 2;
        yp[0] = make_float4(a0, a1, a2, a3);
        yp[1] = make_float4(a4, a5, a6, a7);
        if (yh) {
            half2 h0 = __floats2half2_rn(a0, a1);
            half2 h1 = __floats2half2_rn(a2, a3);
            half2 h2 = __floats2half2_rn(a4, a5);
            half2 h3 = __floats2half2_rn(a6, a7);
            uint4 o;
            o.x = *reinterpret_cast<unsigned*>(&h0);
            o.y = *reinterpret_cast<unsigned*>(&h1);
            o.z = *reinterpret_cast<unsigned*>(&h2);
            o.w = *reinterpret_cast<unsigned*>(&h3);
            reinterpret_cast<uint4*>(yh)[(size_t)r * ROWU4 + i4] = o;
        }
    }
}

// Persistent GEMM: W' staged in smem once per CTA; loop over nodes.
// 256 threads = 8 warps. warp w -> o-group (8 outputs), lane l -> b-pair (2 batches).
// Per node per thread: 2b x 8o tile via packed f32x2 over o.
__global__ void __launch_bounds__(256) k_gemm(
    const float* __restrict__ x0, const float* __restrict__ x1a,
    const float* __restrict__ ya, const float* __restrict__ x1b,
    const float* __restrict__ yb, const float* __restrict__ wm,
    const float* __restrict__ bias, float* __restrict__ out) {
    extern __shared__ float sw[];   // [330][64]
    int t = threadIdx.x;
    int w = t >> 5, l = t & 31;
    int o0 = w * 8;
    int b0 = l * 2;

    for (int i = t; i < DM_ * O_; i += 256) sw[i] = wm[i];
    __syncthreads();

    float bs[8];
#pragma unroll
    for (int k = 0; k < 8; k++) bs[k] = bias[o0 + k];

    const float* xs0 = x0;
    const float* xs1 = x1a;
    const float* xs2 = ya;
    const float* xs3 = x1b;
    const float* xs4 = yb;

    for (int n = blockIdx.x; n < N_; n += gridDim.x) {
        unsigned long long acc[2][4];
#pragma unroll
        for (int bi = 0; bi < 2; bi++)
#pragma unroll
            for (int op = 0; op < 4; op++) acc[bi][op] = 0ULL;

        size_t rowbase = (size_t)n * F_;
        const float2* xp[5];
        xp[0] = reinterpret_cast<const float2*>(xs0 + rowbase) + l;
        xp[1] = reinterpret_cast<const float2*>(xs1 + rowbase) + l;
        xp[2] = reinterpret_cast<const float2*>(xs2 + rowbase) + l;
        xp[3] = reinterpret_cast<const float2*>(xs3 + rowbase) + l;
        xp[4] = reinterpret_cast<const float2*>(xs4 + rowbase) + l;

        for (int d = 0; d < D_; d++) {
#pragma unroll
            for (int m = 0; m < 5; m++) {
                float2 xv = __ldg(xp[m] + d * 32);
                unsigned long long xx0 = pack2(xv.x, xv.x);
                unsigned long long xx1 = pack2(xv.y, xv.y);
                const unsigned long long* wp = reinterpret_cast<const unsigned long long*>(
                    sw + (d * 5 + m) * 64 + o0);
                unsigned long long w0 = wp[0], w1 = wp[1], w2 = wp[2], w3 = wp[3];
                acc[0][0] = fma2(xx0, w0, acc[0][0]);
                acc[0][1] = fma2(xx0, w1, acc[0][1]);
                acc[0][2] = fma2(xx0, w2, acc[0][2]);
                acc[0][3] = fma2(xx0, w3, acc[0][3]);
                acc[1][0] = fma2(xx1, w0, acc[1][0]);
                acc[1][1] = fma2(xx1, w1, acc[1][1]);
                acc[1][2] = fma2(xx1, w2, acc[1][2]);
                acc[1][3] = fma2(xx1, w3, acc[1][3]);
            }
        }

#pragma unroll
        for (int bi = 0; bi < 2; bi++) {
            float* orow = out + (size_t)(b0 + bi) * ((size_t)N_ * O_) + (size_t)n * O_ + o0;
            float2 v0 = unpack2(acc[bi][0]);
            float2 v1 = unpack2(acc[bi][1]);
            float2 v2 = unpack2(acc[bi][2]);
            float2 v3 = unpack2(acc[bi][3]);
            float4 r0 = make_float4(v0.x + bs[0], v0.y + bs[1], v1.x + bs[2], v1.y + bs[3]);
            float4 r1 = make_float4(v2.x + bs[4], v2.y + bs[5], v3.x + bs[6], v3.y + bs[7]);
            reinterpret_cast<float4*>(orow)[0] = r0;
            reinterpret_cast<float4*>(orow)[1] = r1;
        }
    }
}

// ---------------- launch ----------------
extern "C" void kernel_launch(void* const* d_in, const int* in_sizes, int n_in,
                              void* d_out, int out_size) {
    const float* inputs = (const float*)d_in[0];
    const float* weight = (const float*)d_in[2];
    const float* biases = (const float*)d_in[3];
    const float* vals0  = (const float*)d_in[4];
    const float* vals1  = (const float*)d_in[5];
    const int*   rows0  = (const int*)d_in[6];
    const int*   cols0  = (const int*)d_in[7];
    const int*   rows1  = (const int*)d_in[8];
    const int*   cols1  = (const int*)d_in[9];
    float* out = (float*)d_out;

    float *x0, *x1a, *ya, *x1b, *yb, *wm, *valS;
    __half *x0h, *xht;
    int *cnt, *rp, *cur, *colS;
    cudaGetSymbolAddress((void**)&x0,  g_x0);
    cudaGetSymbolAddress((void**)&x1a, g_x1a);
    cudaGetSymbolAddress((void**)&ya,  g_ya);
    cudaGetSymbolAddress((void**)&x1b, g_x1b);
    cudaGetSymbolAddress((void**)&yb,  g_yb);
    cudaGetSymbolAddress((void**)&x0h, g_x0h);
    cudaGetSymbolAddress((void**)&xht, g_xht);
    cudaGetSymbolAddress((void**)&wm,  g_wmod);
    cudaGetSymbolAddress((void**)&cnt,  g_cnt);
    cudaGetSymbolAddress((void**)&rp,   g_rp);
    cudaGetSymbolAddress((void**)&cur,  g_cur);
    cudaGetSymbolAddress((void**)&colS, g_colS);
    cudaGetSymbolAddress((void**)&valS, g_valS);

    const int* rowsArr[2] = {rows0, rows1};
    const int* colsArr[2] = {cols0, cols1};
    const float* valsArr[2] = {vals0, vals1};

    k_wmod<<<(DM_ * O_ + 255) / 256, 256>>>(weight, wm);
    k_transpose<<<N_, 256>>>(inputs, x0, x0h);

    for (int s = 0; s < 2; s++) {
        int* cnt_s  = cnt + (size_t)s * N_;
        int* rp_s   = rp + (size_t)s * (N_ + 1);
        int* cur_s  = cur + (size_t)s * N_;
        int* colS_s = colS + (size_t)s * E_;
        float* valS_s = valS + (size_t)s * E_;
        k_zero_int<<<(N_ + 255) / 256, 256>>>(cnt_s, N_);
        k_hist<<<(E_ + 255) / 256, 256>>>(rowsArr[s], cnt_s);
        k_scan<<<1, 1024>>>(cnt_s, rp_s, cur_s);
        k_scatter<<<(E_ + 255) / 256, 256>>>(rowsArr[s], colsArr[s], valsArr[s],
                                             cur_s, colS_s, valS_s);
    }

    int* rp0 = rp;
    int* rp1 = rp + (N_ + 1);
    int* colS0 = colS;
    int* colS1 = colS + E_;
    float* valS0 = valS;
    float* valS1 = valS + E_;

    dim3 gs(N_, 2);
    k_spmm_h<<<gs, 288>>>(rp0, colS0, valS0, x0h, x1a, xht);   // x1a (+fp16)
    k_spmm_h<<<gs, 288>>>(rp0, colS0, valS0, xht, ya, (__half*)nullptr);
    k_spmm_h<<<gs, 288>>>(rp1, colS1, valS1, x0h, x1b, xht);   // x1b (+fp16)
    k_spmm_h<<<gs, 288>>>(rp1, colS1, valS1, xht, yb, (__half*)nullptr);

    const int smem_gemm = DM_ * O_ * 4;  // 84480 B
    cudaFuncSetAttribute(k_gemm, cudaFuncAttributeMaxDynamicSharedMemorySize, smem_gemm);
    k_gemm<<<296, 256, smem_gemm>>>(x0, x1a, ya, x1b, yb, wm, biases, out);
}

// round 7
// speedup vs baseline: 5.0928x; 2.9898x over previous
#include <cuda_runtime.h>
#include <cuda_fp16.h>
#include <cstdint>

// ---------------- problem constants ----------------
#define B_   64
#define N_   10000
#define D_   66
#define E_   160000
#define O_   64
#define DPAD 72              // padded per-matrix K stride (zeros at d>=66)
#define FH   4608            // halves per x row = 64*72
#define RU4  576             // uint4 per x row
#define KPAD 384             // W'^T row length (zeros padded)
#define KS   392             // smem-padded W'^T row (bank-conflict-free)
#define NPAIR 5000
#define GEMM_GRID 296

// ---------------- scratch ----------------
__device__ __half g_x0h [46080000];
__device__ __half g_x1a [46080000];
__device__ __half g_ya  [46080000];
__device__ __half g_x1b [46080000];
__device__ __half g_yb  [46080000];
__device__ __half g_wt  [64 * KPAD];   // W'^T fp16, [o][k=m*72+d], zeros padded

__device__ int   g_cnt [2][N_];
__device__ int   g_rp  [2][N_ + 1];
__device__ int   g_cur [2][N_];
__device__ int   g_colS[2][E_];
__device__ float g_valS[2][E_];

// ---------------- small kernels ----------------

// W'^T fp16 [64][KPAD], k = m*72 + d ; fold x2 = 2*spmm(x1) - x0 into weights
__global__ void k_wt(const float* __restrict__ w, __half* __restrict__ wt) {
    int i = blockIdx.x * blockDim.x + threadIdx.x;
    if (i >= 64 * KPAD) return;
    int o = i / KPAD, k = i - o * KPAD;
    int m = k / DPAD, d = k - m * DPAD;
    float v = 0.f;
    if (m < 5 && d < D_) {
        if (m == 0)
            v = w[(d * 5 + 0) * 64 + o] - w[(d * 5 + 2) * 64 + o] - w[(d * 5 + 4) * 64 + o];
        else if (m == 2 || m == 4)
            v = 2.0f * w[(d * 5 + m) * 64 + o];
        else
            v = w[(d * 5 + m) * 64 + o];
    }
    wt[i] = __float2half_rn(v);
}

// x0h[n][b*72+d] = inputs[b][n*66+d], fp16, zeros at d>=66
__global__ void k_transpose(const float* __restrict__ in, uint4* __restrict__ x0h) {
    __shared__ float s[B_ * D_];
    int n = blockIdx.x;
    for (int idx = threadIdx.x; idx < B_ * D_; idx += 256) {
        int b = idx / D_, d = idx - b * D_;
        s[idx] = in[(size_t)b * (N_ * D_) + (size_t)n * D_ + d];
    }
    __syncthreads();
    for (int u = threadIdx.x; u < RU4; u += 256) {
        int f0 = u * 8;
        int b = f0 / DPAD, dd = f0 - b * DPAD;
        unsigned q[4];
#pragma unroll
        for (int j = 0; j < 4; j++) {
            int d0 = dd + 2 * j, d1 = d0 + 1;
            float v0 = (d0 < D_) ? s[b * D_ + d0] : 0.f;
            float v1 = (d1 < D_) ? s[b * D_ + d1] : 0.f;
            half2 h = __floats2half2_rn(v0, v1);
            q[j] = *reinterpret_cast<unsigned*>(&h);
        }
        x0h[(size_t)n * RU4 + u] = make_uint4(q[0], q[1], q[2], q[3]);
    }
}

__global__ void k_zero_int(int* __restrict__ p, int n) {
    int i = blockIdx.x * blockDim.x + threadIdx.x;
    if (i < n) p[i] = 0;
}
__global__ void k_hist(const int* __restrict__ rows, int* __restrict__ cnt) {
    int e = blockIdx.x * blockDim.x + threadIdx.x;
    if (e < E_) atomicAdd(&cnt[rows[e]], 1);
}
__global__ void k_scan(const int* __restrict__ cnt, int* __restrict__ rowptr,
                       int* __restrict__ cursor) {
    __shared__ int part[1024];
    const int CH = 10;
    int t = threadIdx.x;
    int base = t * CH;
    int loc[CH];
    int s = 0;
#pragma unroll
    for (int j = 0; j < CH; j++) {
        int i = base + j;
        int c = (i < N_) ? cnt[i] : 0;
        loc[j] = c;
        s += c;
    }
    part[t] = s;
    __syncthreads();
    for (int off = 1; off < 1024; off <<= 1) {
        int v = (t >= off) ? part[t - off] : 0;
        __syncthreads();
        part[t] += v;
        __syncthreads();
    }
    int off0 = (t > 0) ? part[t - 1] : 0;
#pragma unroll
    for (int j = 0; j < CH; j++) {
        int i = base + j;
        if (i < N_) {
            rowptr[i] = off0;
            cursor[i] = off0;
            off0 += loc[j];
        }
    }
    if (t == 1023) rowptr[N_] = part[1023];
}
__global__ void k_scatter(const int* __restrict__ rows, const int* __restrict__ cols,
                          const float* __restrict__ vals, int* __restrict__ cursor,
                          int* __restrict__ colS, float* __restrict__ valS) {
    int e = blockIdx.x * blockDim.x + threadIdx.x;
    if (e < E_) {
        int r = rows[e];
        int p = atomicAdd(&cursor[r], 1);
        colS[p] = cols[e];
        valS[p] = vals[e];
    }
}

// CSR SpMM: fp16 gather, fp32 accum, fp16 out. block = (row, half-row tile of 288 u4)
__global__ void __launch_bounds__(288) k_spmm_h(
    const int* __restrict__ rowptr, const int* __restrict__ colS,
    const float* __restrict__ valS, const uint4* __restrict__ xh,
    uint4* __restrict__ yh) {
    __shared__ int   sc[288];
    __shared__ float sv[288];
    int r = blockIdx.x;
    int t = threadIdx.x;
    int i4 = blockIdx.y * 288 + t;
    int e0 = rowptr[r], e1 = rowptr[r + 1];

    float a0 = 0.f, a1 = 0.f, a2 = 0.f, a3 = 0.f;
    float a4 = 0.f, a5 = 0.f, a6 = 0.f, a7 = 0.f;

    for (int es = e0; es < e1; es += 288) {
        int ne = min(288, e1 - es);
        if (t < ne) { sc[t] = colS[es + t]; sv[t] = valS[es + t]; }
        __syncthreads();
#pragma unroll 4
        for (int j = 0; j < ne; j++) {
            int c = sc[j];
            float v = sv[j];
            uint4 p = __ldg(xh + (size_t)c * RU4 + i4);
            float2 f0 = __half22float2(*reinterpret_cast<half2*>(&p.x));
            float2 f1 = __half22float2(*reinterpret_cast<half2*>(&p.y));
            float2 f2 = __half22float2(*reinterpret_cast<half2*>(&p.z));
            float2 f3 = __half22float2(*reinterpret_cast<half2*>(&p.w));
            a0 += v * f0.x; a1 += v * f0.y;
            a2 += v * f1.x; a3 += v * f1.y;
            a4 += v * f2.x; a5 += v * f2.y;
            a6 += v * f3.x; a7 += v * f3.y;
        }
        __syncthreads();
    }
    half2 h0 = __floats2half2_rn(a0, a1);
    half2 h1 = __floats2half2_rn(a2, a3);
    half2 h2 = __floats2half2_rn(a4, a5);
    half2 h3 = __floats2half2_rn(a6, a7);
    uint4 o;
    o.x = *reinterpret_cast<unsigned*>(&h0);
    o.y = *reinterpret_cast<unsigned*>(&h1);
    o.z = *reinterpret_cast<unsigned*>(&h2);
    o.w = *reinterpret_cast<unsigned*>(&h3);
    yh[(size_t)r * RU4 + i4] = o;
}

// ---------------- HMMA GEMM (mma.sync m16n8k16, arch-portable) ----------------
// Per tile: 2 nodes. A[128 rows (p*64+b) x 368 k] fp16 read directly from global,
// B = W'^T [64 x 368] fp16 in smem. 8 warps: warp w -> 16 rows; k-loop 23 steps,
// n-loop 8 groups of 8.
__global__ void __launch_bounds__(256, 2) k_gemm_mma(
    const __half* __restrict__ x0, const __half* __restrict__ x1a,
    const __half* __restrict__ ya, const __half* __restrict__ x1b,
    const __half* __restrict__ yb, const __half* __restrict__ wt,
    const float* __restrict__ bias, float* __restrict__ out) {
    extern __shared__ __half sB[];   // [64][KS]
    int t = threadIdx.x, wid = t >> 5, lane = t & 31;
    int g = lane >> 2, tid4 = lane & 3;

    // stage W'^T (once per CTA), padded rows for conflict-free frag loads
    const uint4* wt4 = reinterpret_cast<const uint4*>(wt);
    for (int i = t; i < 3072; i += 256) {
        int r = i / 48, c = i - r * 48;
        *reinterpret_cast<uint4*>(sB + r * KS + c * 8) = wt4[i];
    }
    __syncthreads();

    int p = wid >> 2;               // node within pair
    int b_lo = (wid & 3) * 16 + g;  // batch row (lo); hi = +8
    const __half* xs[5] = {x0, x1a, ya, x1b, yb};

    for (int tile = blockIdx.x; tile < NPAIR; tile += gridDim.x) {
        int n = tile * 2 + p;
        size_t baseL = (size_t)n * FH + (size_t)b_lo * DPAD + tid4 * 2;
        size_t baseH = baseL + 8 * DPAD;

        float acc[8][4];
#pragma unroll
        for (int ng = 0; ng < 8; ng++)
#pragma unroll
            for (int q = 0; q < 4; q++) acc[ng][q] = 0.f;

#pragma unroll
        for (int ks = 0; ks < 23; ks++) {
            const int klo = ks * 16;
            const int khi = klo + 8;
            const int mlo = klo / DPAD, dlo = klo - mlo * DPAD;
            const int mhi = khi / DPAD, dhi = khi - mhi * DPAD;
            // A frags: {row_lo,klo},{row_hi,klo},{row_lo,khi},{row_hi,khi}
            unsigned a0, a1, a2, a3;
            a0 = *reinterpret_cast<const unsigned*>(xs[mlo] + baseL + dlo);
            a1 = *reinterpret_cast<const unsigned*>(xs[mlo] + baseH + dlo);
            if (mhi < 5) {
                a2 = *reinterpret_cast<const unsigned*>(xs[mhi] + baseL + dhi);
                a3 = *reinterpret_cast<const unsigned*>(xs[mhi] + baseH + dhi);
            } else {
                a2 = 0u; a3 = 0u;
            }
#pragma unroll
            for (int ng = 0; ng < 8; ng++) {
                const __half* bp = sB + (ng * 8 + g) * KS + klo + tid4 * 2;
                unsigned b0 = *reinterpret_cast<const unsigned*>(bp);
                unsigned b1 = *reinterpret_cast<const unsigned*>(bp + 8);
                asm volatile(
                    "mma.sync.aligned.m16n8k16.row.col.f32.f16.f16.f32 "
                    "{%0,%1,%2,%3}, {%4,%5,%6,%7}, {%8,%9}, {%0,%1,%2,%3};"
                    : "+f"(acc[ng][0]), "+f"(acc[ng][1]),
                      "+f"(acc[ng][2]), "+f"(acc[ng][3])
                    : "r"(a0), "r"(a1), "r"(a2), "r"(a3), "r"(b0), "r"(b1));
            }
        }

        // epilogue: D[g][tid4*2,+1] and D[g+8][..] per n-group
        float* orow_lo = out + (size_t)b_lo * ((size_t)N_ * O_) + (size_t)n * O_;
        float* orow_hi = orow_lo + 8 * ((size_t)N_ * O_);
#pragma unroll
        for (int ng = 0; ng < 8; ng++) {
            int col = ng * 8 + tid4 * 2;
            float2 bv = __ldg(reinterpret_cast<const float2*>(bias + col));
            float2 vlo = make_float2(acc[ng][0] + bv.x, acc[ng][1] + bv.y);
            float2 vhi = make_float2(acc[ng][2] + bv.x, acc[ng][3] + bv.y);
            *reinterpret_cast<float2*>(orow_lo + col) = vlo;
            *reinterpret_cast<float2*>(orow_hi + col) = vhi;
        }
    }
}

// ---------------- launch ----------------
extern "C" void kernel_launch(void* const* d_in, const int* in_sizes, int n_in,
                              void* d_out, int out_size) {
    const float* inputs = (const float*)d_in[0];
    const float* weight = (const float*)d_in[2];
    const float* biases = (const float*)d_in[3];
    const float* vals0  = (const float*)d_in[4];
    const float* vals1  = (const float*)d_in[5];
    const int*   rows0  = (const int*)d_in[6];
    const int*   cols0  = (const int*)d_in[7];
    const int*   rows1  = (const int*)d_in[8];
    const int*   cols1  = (const int*)d_in[9];
    float* out = (float*)d_out;

    __half *x0h, *x1a, *ya, *x1b, *yb, *wt;
    float* valS;
    int *cnt, *rp, *cur, *colS;
    cudaGetSymbolAddress((void**)&x0h, g_x0h);
    cudaGetSymbolAddress((void**)&x1a, g_x1a);
    cudaGetSymbolAddress((void**)&ya,  g_ya);
    cudaGetSymbolAddress((void**)&x1b, g_x1b);
    cudaGetSymbolAddress((void**)&yb,  g_yb);
    cudaGetSymbolAddress((void**)&wt,  g_wt);
    cudaGetSymbolAddress((void**)&cnt,  g_cnt);
    cudaGetSymbolAddress((void**)&rp,   g_rp);
    cudaGetSymbolAddress((void**)&cur,  g_cur);
    cudaGetSymbolAddress((void**)&colS, g_colS);
    cudaGetSymbolAddress((void**)&valS, g_valS);

    const int* rowsArr[2] = {rows0, rows1};
    const int* colsArr[2] = {cols0, cols1};
    const float* valsArr[2] = {vals0, vals1};

    k_wt<<<(64 * KPAD + 255) / 256, 256>>>(weight, wt);
    k_transpose<<<N_, 256>>>(inputs, (uint4*)x0h);

    for (int s = 0; s < 2; s++) {
        int* cnt_s  = cnt + (size_t)s * N_;
        int* rp_s   = rp + (size_t)s * (N_ + 1);
        int* cur_s  = cur + (size_t)s * N_;
        int* colS_s = colS + (size_t)s * E_;
        float* valS_s = valS + (size_t)s * E_;
        k_zero_int<<<(N_ + 255) / 256, 256>>>(cnt_s, N_);
        k_hist<<<(E_ + 255) / 256, 256>>>(rowsArr[s], cnt_s);
        k_scan<<<1, 1024>>>(cnt_s, rp_s, cur_s);
        k_scatter<<<(E_ + 255) / 256, 256>>>(rowsArr[s], colsArr[s], valsArr[s],
                                             cur_s, colS_s, valS_s);
    }

    int* rp0 = rp;
    int* rp1 = rp + (N_ + 1);
    int* colS0 = colS;
    int* colS1 = colS + E_;
    float* valS0 = valS;
    float* valS1 = valS + E_;

    dim3 gs(N_, 2);
    k_spmm_h<<<gs, 288>>>(rp0, colS0, valS0, (const uint4*)x0h, (uint4*)x1a);
    k_spmm_h<<<gs, 288>>>(rp0, colS0, valS0, (const uint4*)x1a, (uint4*)ya);
    k_spmm_h<<<gs, 288>>>(rp1, colS1, valS1, (const uint4*)x0h, (uint4*)x1b);
    k_spmm_h<<<gs, 288>>>(rp1, colS1, valS1, (const uint4*)x1b, (uint4*)yb);

    const int smem_gemm = 64 * KS * 2;  // 50176 B
    cudaFuncSetAttribute(k_gemm_mma, cudaFuncAttributeMaxDynamicSharedMemorySize, smem_gemm);
    k_gemm_mma<<<GEMM_GRID, 256, smem_gemm>>>(x0h, x1a, ya, x1b, yb, wt, biases, out);
}

// round 8
// speedup vs baseline: 5.3525x; 1.0510x over previous
#include <cuda_runtime.h>
#include <cuda_fp16.h>
#include <cstdint>

// ---------------- problem constants ----------------
#define B_   64
#define N_   10000
#define D_   66
#define E_   160000
#define O_   64
#define RH   4224            // halves per x row = 64*66 (unpadded)
#define RU4  528             // uint4 per x row
#define U4T  264             // uint4 per SpMM feature tile (2 tiles)
#define KPAD 384             // W'^T logical row length (k=m*72+d, zeros padded)
#define KS   392             // smem-padded W'^T row (bank-conflict-free)
#define NPAIR 5000
#define GEMM_GRID 296

// ---------------- scratch (slack for GEMM tail overreads) ----------------
__device__ __half g_x0h [42241024];
__device__ __half g_x1a [42241024];
__device__ __half g_ya  [42241024];
__device__ __half g_x1b [42241024];
__device__ __half g_yb  [42241024];
__device__ __half g_wt  [64 * KPAD];   // W'^T fp16, [o][k=m*72+d], zeros padded

__device__ int   g_cnt [2][N_];
__device__ int   g_rp  [2][N_ + 1];
__device__ int   g_cur [2][N_];
__device__ int   g_colS[2][E_];
__device__ float g_valS[2][E_];

// ---------------- small kernels ----------------

// W'^T fp16 [64][KPAD], logical k = m*72 + d ; folds x2 = 2*spmm(x1) - x0
__global__ void k_wt(const float* __restrict__ w, __half* __restrict__ wt) {
    int i = blockIdx.x * blockDim.x + threadIdx.x;
    if (i >= 64 * KPAD) return;
    int o = i / KPAD, k = i - o * KPAD;
    int m = k / 72, d = k - m * 72;
    float v = 0.f;
    if (m < 5 && d < D_) {
        if (m == 0)
            v = w[(d * 5 + 0) * 64 + o] - w[(d * 5 + 2) * 64 + o] - w[(d * 5 + 4) * 64 + o];
        else if (m == 2 || m == 4)
            v = 2.0f * w[(d * 5 + m) * 64 + o];
        else
            v = w[(d * 5 + m) * 64 + o];
    }
    wt[i] = __float2half_rn(v);
}

// x0h[n][b*66+d] = inputs[b][n*66+d]  (fp16, unpadded, b-major)
__global__ void k_transpose(const float* __restrict__ in, half2* __restrict__ x0h) {
    int n = blockIdx.x;
    for (int j = threadIdx.x; j < RH / 2; j += 256) {
        int i = 2 * j;
        int b = i / D_, d = i - b * D_;
        float2 v = *reinterpret_cast<const float2*>(in + (size_t)b * (N_ * D_) +
                                                    (size_t)n * D_ + d);
        x0h[(size_t)n * (RH / 2) + j] = __floats2half2_rn(v.x, v.y);
    }
}

__global__ void k_zero_int(int* __restrict__ p, int n) {
    int i = blockIdx.x * blockDim.x + threadIdx.x;
    if (i < n) p[i] = 0;
}
// both supports in one launch
__global__ void k_hist2(const int* __restrict__ rows0, const int* __restrict__ rows1,
                        int* __restrict__ cnt) {
    int e = blockIdx.x * blockDim.x + threadIdx.x;
    if (e < E_) atomicAdd(&cnt[rows0[e]], 1);
    else if (e < 2 * E_) atomicAdd(&cnt[N_ + rows1[e - E_]], 1);
}
// grid = 2 blocks, one per support
__global__ void k_scan(const int* __restrict__ cnt_all, int* __restrict__ rp_all,
                       int* __restrict__ cur_all) {
    __shared__ int part[1024];
    const int CH = 10;
    const int s = blockIdx.x;
    const int* cnt = cnt_all + s * N_;
    int* rowptr = rp_all + s * (N_ + 1);
    int* cursor = cur_all + s * N_;
    int t = threadIdx.x;
    int base = t * CH;
    int loc[CH];
    int acc = 0;
#pragma unroll
    for (int j = 0; j < CH; j++) {
        int i = base + j;
        int c = (i < N_) ? cnt[i] : 0;
        loc[j] = c;
        acc += c;
    }
    part[t] = acc;
    __syncthreads();
    for (int off = 1; off < 1024; off <<= 1) {
        int v = (t >= off) ? part[t - off] : 0;
        __syncthreads();
        part[t] += v;
        __syncthreads();
    }
    int off0 = (t > 0) ? part[t - 1] : 0;
#pragma unroll
    for (int j = 0; j < CH; j++) {
        int i = base + j;
        if (i < N_) {
            rowptr[i] = off0;
            cursor[i] = off0;
            off0 += loc[j];
        }
    }
    if (t == 1023) rowptr[N_] = part[1023];
}
__global__ void k_scatter2(const int* __restrict__ rows0, const int* __restrict__ cols0,
                           const float* __restrict__ vals0,
                           const int* __restrict__ rows1, const int* __restrict__ cols1,
                           const float* __restrict__ vals1,
                           int* __restrict__ cur_all, int* __restrict__ colS_all,
                           float* __restrict__ valS_all) {
    int e = blockIdx.x * blockDim.x + threadIdx.x;
    if (e < E_) {
        int r = rows0[e];
        int p = atomicAdd(&cur_all[r], 1);
        colS_all[p] = cols0[e];
        valS_all[p] = vals0[e];
    } else if (e < 2 * E_) {
        int ee = e - E_;
        int r = rows1[ee];
        int p = atomicAdd(&cur_all[N_ + r], 1);
        colS_all[E_ + p] = cols1[ee];
        valS_all[E_ + p] = vals1[ee];
    }
}

// CSR SpMM: fp16 gather, fp32 accum, fp16 out. block = (row, tile of 264 u4)
__global__ void __launch_bounds__(288) k_spmm_h(
    const int* __restrict__ rowptr, const int* __restrict__ colS,
    const float* __restrict__ valS, const uint4* __restrict__ xh,
    uint4* __restrict__ yh) {
    __shared__ int   sc[288];
    __shared__ float sv[288];
    int r = blockIdx.x;
    int t = threadIdx.x;
    int i4 = blockIdx.y * U4T + t;
    bool act = (t < U4T);
    int e0 = rowptr[r], e1 = rowptr[r + 1];

    float a0 = 0.f, a1 = 0.f, a2 = 0.f, a3 = 0.f;
    float a4 = 0.f, a5 = 0.f, a6 = 0.f, a7 = 0.f;

    for (int es = e0; es < e1; es += 288) {
        int ne = min(288, e1 - es);
        if (t < ne) { sc[t] = colS[es + t]; sv[t] = valS[es + t]; }
        __syncthreads();
        if (act) {
#pragma unroll 4
            for (int j = 0; j < ne; j++) {
                int c = sc[j];
                float v = sv[j];
                uint4 p = __ldg(xh + (size_t)c * RU4 + i4);
                float2 f0 = __half22float2(*reinterpret_cast<half2*>(&p.x));
                float2 f1 = __half22float2(*reinterpret_cast<half2*>(&p.y));
                float2 f2 = __half22float2(*reinterpret_cast<half2*>(&p.z));
                float2 f3 = __half22float2(*reinterpret_cast<half2*>(&p.w));
                a0 += v * f0.x; a1 += v * f0.y;
                a2 += v * f1.x; a3 += v * f1.y;
                a4 += v * f2.x; a5 += v * f2.y;
                a6 += v * f3.x; a7 += v * f3.y;
            }
        }
        __syncthreads();
    }
    if (act) {
        half2 h0 = __floats2half2_rn(a0, a1);
        half2 h1 = __floats2half2_rn(a2, a3);
        half2 h2 = __floats2half2_rn(a4, a5);
        half2 h3 = __floats2half2_rn(a6, a7);
        uint4 o;
        o.x = *reinterpret_cast<unsigned*>(&h0);
        o.y = *reinterpret_cast<unsigned*>(&h1);
        o.z = *reinterpret_cast<unsigned*>(&h2);
        o.w = *reinterpret_cast<unsigned*>(&h3);
        yh[(size_t)r * RU4 + i4] = o;
    }
}

// ---------------- HMMA GEMM (mma.sync m16n8k16) ----------------
// Logical k = m*72+d lives in B (zeros at d>=66); A is unpadded (stride 66).
// Every 8-half fragment is within one m (72 % 8 == 0), so m, d are compile-time.
// Fragment halves with d in [66,72) read garbage but hit zero B columns.
__global__ void __launch_bounds__(256, 2) k_gemm_mma(
    const __half* __restrict__ x0, const __half* __restrict__ x1a,
    const __half* __restrict__ ya, const __half* __restrict__ x1b,
    const __half* __restrict__ yb, const __half* __restrict__ wt,
    const float* __restrict__ bias, float* __restrict__ out) {
    extern __shared__ __half sB[];   // [64][KS]
    int t = threadIdx.x, wid = t >> 5, lane = t & 31;
    int g = lane >> 2, tid4 = lane & 3;

    const uint4* wt4 = reinterpret_cast<const uint4*>(wt);
    for (int i = t; i < 3072; i += 256) {
        int r = i / 48, c = i - r * 48;
        *reinterpret_cast<uint4*>(sB + r * KS + c * 8) = wt4[i];
    }
    __syncthreads();

    int p = wid >> 2;               // node within pair
    int b_lo = (wid & 3) * 16 + g;  // batch row (lo); hi = +8
    const __half* xs[5] = {x0, x1a, ya, x1b, yb};

    for (int tile = blockIdx.x; tile < NPAIR; tile += gridDim.x) {
        int n = tile * 2 + p;
        size_t baseL = (size_t)n * RH + (size_t)b_lo * D_ + tid4 * 2;
        size_t baseH = baseL + 8 * D_;

        float acc[8][4];
#pragma unroll
        for (int ng = 0; ng < 8; ng++)
#pragma unroll
            for (int q = 0; q < 4; q++) acc[ng][q] = 0.f;

#pragma unroll
        for (int ks = 0; ks < 23; ks++) {
            const int klo = ks * 16;
            const int khi = klo + 8;
            const int mlo = klo / 72, dlo = klo - mlo * 72;
            const int mhi = khi / 72, dhi = khi - mhi * 72;
            unsigned a0, a1, a2, a3;
            a0 = *reinterpret_cast<const unsigned*>(xs[mlo] + baseL + dlo);
            a1 = *reinterpret_cast<const unsigned*>(xs[mlo] + baseH + dlo);
            if (mhi < 5) {
                a2 = *reinterpret_cast<const unsigned*>(xs[mhi] + baseL + dhi);
                a3 = *reinterpret_cast<const unsigned*>(xs[mhi] + baseH + dhi);
            } else {
                a2 = 0u; a3 = 0u;
            }
#pragma unroll
            for (int ng = 0; ng < 8; ng++) {
                const __half* bp = sB + (ng * 8 + g) * KS + klo + tid4 * 2;
                unsigned b0 = *reinterpret_cast<const unsigned*>(bp);
                unsigned b1 = *reinterpret_cast<const unsigned*>(bp + 8);
                asm volatile(
                    "mma.sync.aligned.m16n8k16.row.col.f32.f16.f16.f32 "
                    "{%0,%1,%2,%3}, {%4,%5,%6,%7}, {%8,%9}, {%0,%1,%2,%3};"
                    : "+f"(acc[ng][0]), "+f"(acc[ng][1]),
                      "+f"(acc[ng][2]), "+f"(acc[ng][3])
                    : "r"(a0), "r"(a1), "r"(a2), "r"(a3), "r"(b0), "r"(b1));
            }
        }

        float* orow_lo = out + (size_t)b_lo * ((size_t)N_ * O_) + (size_t)n * O_;
        float* orow_hi = orow_lo + 8 * ((size_t)N_ * O_);
#pragma unroll
        for (int ng = 0; ng < 8; ng++) {
            int col = ng * 8 + tid4 * 2;
            float2 bv = __ldg(reinterpret_cast<const float2*>(bias + col));
            float2 vlo = make_float2(acc[ng][0] + bv.x, acc[ng][1] + bv.y);
            float2 vhi = make_float2(acc[ng][2] + bv.x, acc[ng][3] + bv.y);
            *reinterpret_cast<float2*>(orow_lo + col) = vlo;
            *reinterpret_cast<float2*>(orow_hi + col) = vhi;
        }
    }
}

// ---------------- launch ----------------
extern "C" void kernel_launch(void* const* d_in, const int* in_sizes, int n_in,
                              void* d_out, int out_size) {
    const float* inputs = (const float*)d_in[0];
    const float* weight = (const float*)d_in[2];
    const float* biases = (const float*)d_in[3];
    const float* vals0  = (const float*)d_in[4];
    const float* vals1  = (const float*)d_in[5];
    const int*   rows0  = (const int*)d_in[6];
    const int*   cols0  = (const int*)d_in[7];
    const int*   rows1  = (const int*)d_in[8];
    const int*   cols1  = (const int*)d_in[9];
    float* out = (float*)d_out;

    __half *x0h, *x1a, *ya, *x1b, *yb, *wt;
    float* valS;
    int *cnt, *rp, *cur, *colS;
    cudaGetSymbolAddress((void**)&x0h, g_x0h);
    cudaGetSymbolAddress((void**)&x1a, g_x1a);
    cudaGetSymbolAddress((void**)&ya,  g_ya);
    cudaGetSymbolAddress((void**)&x1b, g_x1b);
    cudaGetSymbolAddress((void**)&yb,  g_yb);
    cudaGetSymbolAddress((void**)&wt,  g_wt);
    cudaGetSymbolAddress((void**)&cnt,  g_cnt);
    cudaGetSymbolAddress((void**)&rp,   g_rp);
    cudaGetSymbolAddress((void**)&cur,  g_cur);
    cudaGetSymbolAddress((void**)&colS, g_colS);
    cudaGetSymbolAddress((void**)&valS, g_valS);

    k_wt<<<(64 * KPAD + 255) / 256, 256>>>(weight, wt);
    k_transpose<<<N_, 256>>>(inputs, (half2*)x0h);

    k_zero_int<<<(2 * N_ + 255) / 256, 256>>>(cnt, 2 * N_);
    k_hist2<<<(2 * E_ + 255) / 256, 256>>>(rows0, rows1, cnt);
    k_scan<<<2, 1024>>>(cnt, rp, cur);
    k_scatter2<<<(2 * E_ + 255) / 256, 256>>>(rows0, cols0, vals0,
                                              rows1, cols1, vals1,
                                              cur, colS, valS);

    int* rp0 = rp;
    int* rp1 = rp + (N_ + 1);
    int* colS0 = colS;
    int* colS1 = colS + E_;
    float* valS0 = valS;
    float* valS1 = valS + E_;

    dim3 gs(N_, 2);
    // both stage-1 SpMMs first (x0 stays L2-hot), then stage-2
    k_spmm_h<<<gs, 288>>>(rp0, colS0, valS0, (const uint4*)x0h, (uint4*)x1a);
    k_spmm_h<<<gs, 288>>>(rp1, colS1, valS1, (const uint4*)x0h, (uint4*)x1b);
    k_spmm_h<<<gs, 288>>>(rp0, colS0, valS0, (const uint4*)x1a, (uint4*)ya);
    k_spmm_h<<<gs, 288>>>(rp1, colS1, valS1, (const uint4*)x1b, (uint4*)yb);

    const int smem_gemm = 64 * KS * 2;  // 50176 B
    cudaFuncSetAttribute(k_gemm_mma, cudaFuncAttributeMaxDynamicSharedMemorySize, smem_gemm);
    k_gemm_mma<<<GEMM_GRID, 256, smem_gemm>>>(x0h, x1a, ya, x1b, yb, wt, biases, out);
}